// round 13
// baseline (speedup 1.0000x reference)
#include <cuda_runtime.h>

#define N_NODES   50000
#define N_EDGES   800000
#define D         96
#define OUT_COLS  384            // 4 * D (concat of x,h1,h2,h3)
#define M_TILE    48             // rows per MLP block (smem 75KB -> 3 blocks/SM)
#define IN_LD     100            // padded smem row stride, 16B-aligned rows

#define SCAN_BS   512
#define SCAN_NB   ((N_NODES + SCAN_BS - 1) / SCAN_BS)   // 98

// S_l = out[:, l*96 : (l+1)*96], row stride OUT_COLS. CSR scratch in globals.
__device__ int g_cnt[N_NODES];          // histogram, then fill cursors
__device__ int g_rowptr[N_NODES + 1];
__device__ int g_csr[N_EDGES];          // src ids grouped by dst
__device__ int g_blksum[SCAN_NB];
__device__ int g_blkoff[SCAN_NB];

// ---- packed fp32x2 helpers (FFMA2: 2 fp32 FMA per issue slot) -------------
typedef unsigned long long ull;
__device__ __forceinline__ ull pack2(float lo, float hi) {
    ull r; asm("mov.b64 %0, {%1, %2};" : "=l"(r) : "f"(lo), "f"(hi)); return r;
}
__device__ __forceinline__ void unpack2(ull v, float& lo, float& hi) {
    asm("mov.b64 {%0, %1}, %2;" : "=f"(lo), "=f"(hi) : "l"(v));
}
__device__ __forceinline__ void fma2(ull& d, ull a, ull b) {
    asm("fma.rn.f32x2 %0, %1, %2, %0;" : "+l"(d) : "l"(a), "l"(b));
}

// ---------------------------------------------------------------------------
__global__ void zero_cnt_kernel() {
    int i = blockIdx.x * blockDim.x + threadIdx.x;
    if (i < N_NODES) g_cnt[i] = 0;
}

__global__ void count_kernel(const int* __restrict__ ei) {
    int e = blockIdx.x * blockDim.x + threadIdx.x;
    if (e < N_EDGES) atomicAdd(&g_cnt[ei[N_EDGES + e]], 1);
}

__global__ void scan_a_kernel() {
    __shared__ int sh[SCAN_BS];
    int t = threadIdx.x;
    int i = blockIdx.x * SCAN_BS + t;
    int v = (i < N_NODES) ? g_cnt[i] : 0;
    sh[t] = v;
    __syncthreads();
    for (int off = 1; off < SCAN_BS; off <<= 1) {
        int u = (t >= off) ? sh[t - off] : 0;
        __syncthreads();
        sh[t] += u;
        __syncthreads();
    }
    if (i < N_NODES) g_rowptr[i] = sh[t] - v;
    if (t == SCAN_BS - 1) g_blksum[blockIdx.x] = sh[t];
}

__global__ void scan_b_kernel() {
    __shared__ int sh[128];
    int t = threadIdx.x;
    int v = (t < SCAN_NB) ? g_blksum[t] : 0;
    sh[t] = v;
    __syncthreads();
    for (int off = 1; off < 128; off <<= 1) {
        int u = (t >= off) ? sh[t - off] : 0;
        __syncthreads();
        sh[t] += u;
        __syncthreads();
    }
    if (t < SCAN_NB) g_blkoff[t] = sh[t] - v;
}

__global__ void scan_c_kernel() {
    int i = blockIdx.x * blockDim.x + threadIdx.x;
    if (i < N_NODES) {
        int r = g_rowptr[i] + g_blkoff[i / SCAN_BS];
        g_rowptr[i] = r;
        g_cnt[i]    = r;                 // cursor for fill
    }
    if (i == 0) g_rowptr[N_NODES] = N_EDGES;
}

__global__ void fill_kernel(const int* __restrict__ ei) {
    int e = blockIdx.x * blockDim.x + threadIdx.x;
    if (e >= N_EDGES) return;
    int src = ei[e];
    int dst = ei[N_EDGES + e];
    int pos = atomicAdd(&g_cnt[dst], 1);
    g_csr[pos] = src;
}

// ---------------------------------------------------------------------------
// aggr: next[n] = cur[n] + sum_{src in in(n)} cur[src]; cur has row stride cs.
// selfcopy (optional) receives cur[n] (used for layer 0: S0 = x).
// ---------------------------------------------------------------------------
__global__ void aggr_kernel(const float* __restrict__ cur, int cs,
                            float* __restrict__ selfcopy,
                            float* __restrict__ next) {
    const int n = blockIdx.x * 4 + threadIdx.x / 96;
    const int c = threadIdx.x % 96;
    float self = cur[(size_t)n * cs + c];
    float acc = self;                               // (1+eps)*h with eps=0
    int j   = g_rowptr[n];
    int end = g_rowptr[n + 1];
    for (; j + 4 <= end; j += 4) {
        int s0 = g_csr[j], s1 = g_csr[j + 1], s2 = g_csr[j + 2], s3 = g_csr[j + 3];
        float v0 = __ldg(&cur[(size_t)s0 * cs + c]);
        float v1 = __ldg(&cur[(size_t)s1 * cs + c]);
        float v2 = __ldg(&cur[(size_t)s2 * cs + c]);
        float v3 = __ldg(&cur[(size_t)s3 * cs + c]);
        acc += (v0 + v1) + (v2 + v3);
    }
    for (; j < end; ++j)
        acc += __ldg(&cur[(size_t)g_csr[j] * cs + c]);
    if (selfcopy) selfcopy[(size_t)n * OUT_COLS + c] = self;
    next[(size_t)n * OUT_COLS + c] = acc;
}

// ---------------------------------------------------------------------------
// mlp: slice := relu(slice @ w1 + b1) @ w2 + b2   (in place, per-block safe)
// Block = 48 rows, 256 threads (tx=16, ty=16); micro-tile 3 rows x 6 cols.
// Packed fma.rn.f32x2. Smem 75264B -> 3 blocks/SM -> 6 warps/SMSP.
// ---------------------------------------------------------------------------
__global__ void mlp_kernel(const float* __restrict__ w1, const float* __restrict__ b1,
                           const float* __restrict__ w2, const float* __restrict__ b2,
                           float* __restrict__ slice) {
    extern __shared__ float smem[];
    float* sW   = smem;                    // 96*96
    float* sIn  = sW  + D * D;             // 48*100
    float* sTmp = sIn + M_TILE * IN_LD;    // 48*100

    const int tid = threadIdx.x;
    const int tx  = tid & 15;              // 6 cols each
    const int ty  = tid >> 4;              // 3 rows each
    const int rowBase = blockIdx.x * M_TILE;

    for (int i = tid; i < D * D / 4; i += 256)
        reinterpret_cast<float4*>(sW)[i] = reinterpret_cast<const float4*>(w1)[i];
    for (int i = tid; i < M_TILE * (D / 4); i += 256) {
        int r  = i / (D / 4);
        int cc = i % (D / 4);
        int row = rowBase + r;
        float4 v = make_float4(0.f, 0.f, 0.f, 0.f);
        if (row < N_NODES)
            v = *reinterpret_cast<const float4*>(slice + (size_t)row * OUT_COLS + cc * 4);
        *reinterpret_cast<float4*>(sIn + r * IN_LD + cc * 4) = v;
    }
    __syncthreads();

    ull acc2[3][3];
    const ull z = pack2(0.f, 0.f);

    // ---- phase 1: tmp = relu(in @ w1 + b1) ----
    #pragma unroll
    for (int r = 0; r < 3; ++r)
        #pragma unroll
        for (int jj = 0; jj < 3; ++jj) acc2[r][jj] = z;

    #pragma unroll 2
    for (int k = 0; k < D; k += 4) {
        float4 a4[3];
        #pragma unroll
        for (int r = 0; r < 3; ++r)
            a4[r] = *reinterpret_cast<const float4*>(sIn + (ty * 3 + r) * IN_LD + k);
        #pragma unroll
        for (int kk = 0; kk < 4; ++kk) {
            const float* bp = sW + (k + kk) * D + tx * 6;
            float2 q0 = *reinterpret_cast<const float2*>(bp);
            float2 q1 = *reinterpret_cast<const float2*>(bp + 2);
            float2 q2 = *reinterpret_cast<const float2*>(bp + 4);
            ull bb0 = pack2(q0.x, q0.y), bb1 = pack2(q1.x, q1.y), bb2 = pack2(q2.x, q2.y);
            #pragma unroll
            for (int r = 0; r < 3; ++r) {
                float a = kk == 0 ? a4[r].x : kk == 1 ? a4[r].y : kk == 2 ? a4[r].z : a4[r].w;
                ull a2 = pack2(a, a);
                fma2(acc2[r][0], a2, bb0);
                fma2(acc2[r][1], a2, bb1);
                fma2(acc2[r][2], a2, bb2);
            }
        }
    }
    #pragma unroll
    for (int r = 0; r < 3; ++r) {
        float* tp = sTmp + (ty * 3 + r) * IN_LD + tx * 6;
        #pragma unroll
        for (int jj = 0; jj < 3; ++jj) {
            float lo, hi; unpack2(acc2[r][jj], lo, hi);
            tp[jj * 2 + 0] = fmaxf(lo + b1[tx * 6 + jj * 2 + 0], 0.f);
            tp[jj * 2 + 1] = fmaxf(hi + b1[tx * 6 + jj * 2 + 1], 0.f);
        }
    }
    __syncthreads();

    for (int i = tid; i < D * D / 4; i += 256)
        reinterpret_cast<float4*>(sW)[i] = reinterpret_cast<const float4*>(w2)[i];
    __syncthreads();

    // ---- phase 2: out = tmp @ w2 + b2 ----
    #pragma unroll
    for (int r = 0; r < 3; ++r)
        #pragma unroll
        for (int jj = 0; jj < 3; ++jj) acc2[r][jj] = z;

    #pragma unroll 2
    for (int k = 0; k < D; k += 4) {
        float4 a4[3];
        #pragma unroll
        for (int r = 0; r < 3; ++r)
            a4[r] = *reinterpret_cast<const float4*>(sTmp + (ty * 3 + r) * IN_LD + k);
        #pragma unroll
        for (int kk = 0; kk < 4; ++kk) {
            const float* bp = sW + (k + kk) * D + tx * 6;
            float2 q0 = *reinterpret_cast<const float2*>(bp);
            float2 q1 = *reinterpret_cast<const float2*>(bp + 2);
            float2 q2 = *reinterpret_cast<const float2*>(bp + 4);
            ull bb0 = pack2(q0.x, q0.y), bb1 = pack2(q1.x, q1.y), bb2 = pack2(q2.x, q2.y);
            #pragma unroll
            for (int r = 0; r < 3; ++r) {
                float a = kk == 0 ? a4[r].x : kk == 1 ? a4[r].y : kk == 2 ? a4[r].z : a4[r].w;
                ull a2 = pack2(a, a);
                fma2(acc2[r][0], a2, bb0);
                fma2(acc2[r][1], a2, bb1);
                fma2(acc2[r][2], a2, bb2);
            }
        }
    }

    #pragma unroll
    for (int r = 0; r < 3; ++r) {
        int row = rowBase + ty * 3 + r;
        if (row >= N_NODES) continue;
        float* op = slice + (size_t)row * OUT_COLS + tx * 6;
        #pragma unroll
        for (int jj = 0; jj < 3; ++jj) {
            float lo, hi; unpack2(acc2[r][jj], lo, hi);
            float2 o; o.x = lo + b2[tx * 6 + jj * 2 + 0];
            o.y = hi + b2[tx * 6 + jj * 2 + 1];
            *reinterpret_cast<float2*>(op + jj * 2) = o;
        }
    }
}

// ---------------------------------------------------------------------------
extern "C" void kernel_launch(void* const* d_in, const int* in_sizes, int n_in,
                              void* d_out, int out_size) {
    const float* x  = (const float*)d_in[0];
    const int*   ei = (const int*)d_in[1];
    const float* W[12];
    for (int i = 0; i < 12; ++i) W[i] = (const float*)d_in[2 + i];
    float* out = (float*)d_out;

    const int SMEM_BYTES = (D * D + 2 * M_TILE * IN_LD) * (int)sizeof(float); // 75264
    cudaFuncSetAttribute(mlp_kernel, cudaFuncAttributeMaxDynamicSharedMemorySize, SMEM_BYTES);

    // CSR build (hierarchical scan; all stages full-grid)
    zero_cnt_kernel<<<(N_NODES + 255) / 256, 256>>>();
    count_kernel<<<(N_EDGES + 255) / 256, 256>>>(ei);
    scan_a_kernel<<<SCAN_NB, SCAN_BS>>>();
    scan_b_kernel<<<1, 128>>>();
    scan_c_kernel<<<(N_NODES + 255) / 256, 256>>>();
    fill_kernel<<<(N_EDGES + 255) / 256, 256>>>(ei);

    for (int l = 0; l < 3; ++l) {
        const float* cur = (l == 0) ? x : out + (size_t)l * D;
        int cs           = (l == 0) ? D : OUT_COLS;
        float* selfcopy  = (l == 0) ? out : nullptr;   // S0 = x
        float* agg       = out + (size_t)(l + 1) * D;  // S_{l+1}
        aggr_kernel<<<N_NODES / 4, 384>>>(cur, cs, selfcopy, agg);
        mlp_kernel<<<(N_NODES + M_TILE - 1) / M_TILE, 256, SMEM_BYTES>>>(
            W[4 * l + 0], W[4 * l + 1], W[4 * l + 2], W[4 * l + 3], agg);
    }
}

// round 14
// speedup vs baseline: 1.2046x; 1.2046x over previous
#include <cuda_runtime.h>

#define N_NODES   50000
#define N_EDGES   800000
#define D         96
#define OUT_COLS  384            // 4 * D (concat of x,h1,h2,h3)
#define M_TILE    64             // rows per fused block
#define IN_LD     100            // padded smem row stride (floats), even & 16B rows

#define SCAN_BS   512
#define SCAN_NB   ((N_NODES + SCAN_BS - 1) / SCAN_BS)   // 98

// CSR scratch in globals.
__device__ int g_cnt[N_NODES];
__device__ int g_rowptr[N_NODES + 1];
__device__ int g_csr[N_EDGES];
__device__ int g_blksum[SCAN_NB];
__device__ int g_blkoff[SCAN_NB];

typedef unsigned long long ull;
__device__ __forceinline__ ull pack2(float lo, float hi) {
    ull r; asm("mov.b64 %0, {%1, %2};" : "=l"(r) : "f"(lo), "f"(hi)); return r;
}
__device__ __forceinline__ void unpack2(ull v, float& lo, float& hi) {
    asm("mov.b64 {%0, %1}, %2;" : "=f"(lo), "=f"(hi) : "l"(v));
}
__device__ __forceinline__ void fma2(ull& d, ull a, ull b) {
    asm("fma.rn.f32x2 %0, %1, %2, %0;" : "+l"(d) : "l"(a), "l"(b));
}

// --------------------------- CSR build --------------------------------------
__global__ void zero_cnt_kernel() {
    int i = blockIdx.x * blockDim.x + threadIdx.x;
    if (i < N_NODES) g_cnt[i] = 0;
}
__global__ void count_kernel(const int* __restrict__ ei) {
    int e = blockIdx.x * blockDim.x + threadIdx.x;
    if (e < N_EDGES) atomicAdd(&g_cnt[ei[N_EDGES + e]], 1);
}
__global__ void scan_a_kernel() {
    __shared__ int sh[SCAN_BS];
    int t = threadIdx.x;
    int i = blockIdx.x * SCAN_BS + t;
    int v = (i < N_NODES) ? g_cnt[i] : 0;
    sh[t] = v;
    __syncthreads();
    for (int off = 1; off < SCAN_BS; off <<= 1) {
        int u = (t >= off) ? sh[t - off] : 0;
        __syncthreads();
        sh[t] += u;
        __syncthreads();
    }
    if (i < N_NODES) g_rowptr[i] = sh[t] - v;
    if (t == SCAN_BS - 1) g_blksum[blockIdx.x] = sh[t];
}
__global__ void scan_b_kernel() {
    __shared__ int sh[128];
    int t = threadIdx.x;
    int v = (t < SCAN_NB) ? g_blksum[t] : 0;
    sh[t] = v;
    __syncthreads();
    for (int off = 1; off < 128; off <<= 1) {
        int u = (t >= off) ? sh[t - off] : 0;
        __syncthreads();
        sh[t] += u;
        __syncthreads();
    }
    if (t < SCAN_NB) g_blkoff[t] = sh[t] - v;
}
__global__ void scan_c_kernel() {
    int i = blockIdx.x * blockDim.x + threadIdx.x;
    if (i < N_NODES) {
        int r = g_rowptr[i] + g_blkoff[i / SCAN_BS];
        g_rowptr[i] = r;
        g_cnt[i]    = r;
    }
    if (i == 0) g_rowptr[N_NODES] = N_EDGES;
}
__global__ void fill_kernel(const int* __restrict__ ei) {
    int e = blockIdx.x * blockDim.x + threadIdx.x;
    if (e >= N_EDGES) return;
    int src = ei[e];
    int dst = ei[N_EDGES + e];
    int pos = atomicAdd(&g_cnt[dst], 1);
    g_csr[pos] = src;
}

// ---------------------------------------------------------------------------
// fused layer: for 64 rows, gather CSR aggregation into smem, then
// dst := relu(aggr @ w1 + b1) @ w2 + b2.
// cur: input features, row stride cs (x for layer 0, else an out slice).
// self0: if non-null, receives cur[row] (S0 = x copy, layer 0 only).
// FFMA2 k-pair scheme: acc lanes hold (even-k, odd-k) partial sums.
// sW holds interleaved weights: sW[p*96+j] = (w[2p][j], w[2p+1][j]).
// smem = 36864 + 2*25600 = 88064 B -> 2 blocks/SM.
// ---------------------------------------------------------------------------
__global__ __launch_bounds__(256) void fused_layer_kernel(
        const float* __restrict__ cur, int cs,
        const float* __restrict__ w1, const float* __restrict__ b1,
        const float* __restrict__ w2, const float* __restrict__ b2,
        float* __restrict__ self0, float* __restrict__ dst) {
    extern __shared__ char smem[];
    ull*   sW   = reinterpret_cast<ull*>(smem);                  // 4608 ull
    float* sIn  = reinterpret_cast<float*>(smem + 36864);        // 64*100
    float* sTmp = reinterpret_cast<float*>(smem + 36864 + 25600);// 64*100

    const int tid = threadIdx.x;
    const int tx  = tid & 15;             // 6 output cols each
    const int ty  = tid >> 4;             // 4 output rows each
    const int rowBase = blockIdx.x * M_TILE;
    const int cs4 = cs / 4;
    const float4* curv = reinterpret_cast<const float4*>(cur);

    // ---- interleaved w1 load: sW[p*96+j] = (w1[2p][j], w1[2p+1][j]) ----
    #pragma unroll
    for (int i = 0; i < 18; ++i) {
        int idx = tid + 256 * i;          // 0..4607
        int p = idx / 96, j = idx % 96;
        sW[idx] = pack2(w1[(2 * p) * D + j], w1[(2 * p + 1) * D + j]);
    }

    // ---- gather: sIn[r] = cur[row] + sum_neighbors cur[src] ----
    #pragma unroll
    for (int i = 0; i < 6; ++i) {
        int u = tid + 256 * i;            // 64 rows x 24 float4-chunks
        int r = u / 24, c = u % 24;
        int row = rowBase + r;
        float4 acc = make_float4(0.f, 0.f, 0.f, 0.f);
        if (row < N_NODES) {
            float4 self = __ldg(&curv[(size_t)row * cs4 + c]);
            if (self0)
                *reinterpret_cast<float4*>(self0 + (size_t)row * OUT_COLS + c * 4) = self;
            acc = self;
            int j = g_rowptr[row], end = g_rowptr[row + 1];
            for (; j + 2 <= end; j += 2) {
                int s0 = g_csr[j], s1 = g_csr[j + 1];
                float4 v0 = __ldg(&curv[(size_t)s0 * cs4 + c]);
                float4 v1 = __ldg(&curv[(size_t)s1 * cs4 + c]);
                acc.x += v0.x + v1.x; acc.y += v0.y + v1.y;
                acc.z += v0.z + v1.z; acc.w += v0.w + v1.w;
            }
            if (j < end) {
                float4 v = __ldg(&curv[(size_t)g_csr[j] * cs4 + c]);
                acc.x += v.x; acc.y += v.y; acc.z += v.z; acc.w += v.w;
            }
        }
        *reinterpret_cast<float4*>(sIn + r * IN_LD + c * 4) = acc;
    }
    __syncthreads();

    ull acc2[4][6];
    // ---- phase 1: tmp = relu(in @ w1 + b1) ----
    #pragma unroll
    for (int r = 0; r < 4; ++r)
        #pragma unroll
        for (int j = 0; j < 6; ++j) acc2[r][j] = pack2(0.f, 0.f);

    #pragma unroll 4
    for (int p = 0; p < D / 2; ++p) {
        ull a2[4];
        #pragma unroll
        for (int r = 0; r < 4; ++r)
            a2[r] = *reinterpret_cast<const ull*>(sIn + (ty * 4 + r) * IN_LD + 2 * p);
        const ull* bp = sW + p * 96 + tx * 6;
        ull b0 = bp[0], b1v = bp[1], b2v = bp[2], b3 = bp[3], b4 = bp[4], b5 = bp[5];
        #pragma unroll
        for (int r = 0; r < 4; ++r) {
            fma2(acc2[r][0], a2[r], b0);
            fma2(acc2[r][1], a2[r], b1v);
            fma2(acc2[r][2], a2[r], b2v);
            fma2(acc2[r][3], a2[r], b3);
            fma2(acc2[r][4], a2[r], b4);
            fma2(acc2[r][5], a2[r], b5);
        }
    }
    #pragma unroll
    for (int r = 0; r < 4; ++r) {
        float* tp = sTmp + (ty * 4 + r) * IN_LD + tx * 6;
        #pragma unroll
        for (int j = 0; j < 6; ++j) {
            float lo, hi; unpack2(acc2[r][j], lo, hi);
            tp[j] = fmaxf(lo + hi + b1[tx * 6 + j], 0.f);
        }
    }
    __syncthreads();

    // ---- interleaved w2 load ----
    #pragma unroll
    for (int i = 0; i < 18; ++i) {
        int idx = tid + 256 * i;
        int p = idx / 96, j = idx % 96;
        sW[idx] = pack2(w2[(2 * p) * D + j], w2[(2 * p + 1) * D + j]);
    }
    __syncthreads();

    // ---- phase 2: out = tmp @ w2 + b2 ----
    #pragma unroll
    for (int r = 0; r < 4; ++r)
        #pragma unroll
        for (int j = 0; j < 6; ++j) acc2[r][j] = pack2(0.f, 0.f);

    #pragma unroll 4
    for (int p = 0; p < D / 2; ++p) {
        ull a2[4];
        #pragma unroll
        for (int r = 0; r < 4; ++r)
            a2[r] = *reinterpret_cast<const ull*>(sTmp + (ty * 4 + r) * IN_LD + 2 * p);
        const ull* bp = sW + p * 96 + tx * 6;
        ull b0 = bp[0], b1v = bp[1], b2v = bp[2], b3 = bp[3], b4 = bp[4], b5 = bp[5];
        #pragma unroll
        for (int r = 0; r < 4; ++r) {
            fma2(acc2[r][0], a2[r], b0);
            fma2(acc2[r][1], a2[r], b1v);
            fma2(acc2[r][2], a2[r], b2v);
            fma2(acc2[r][3], a2[r], b3);
            fma2(acc2[r][4], a2[r], b4);
            fma2(acc2[r][5], a2[r], b5);
        }
    }

    #pragma unroll
    for (int r = 0; r < 4; ++r) {
        int row = rowBase + ty * 4 + r;
        if (row >= N_NODES) continue;
        float* op = dst + (size_t)row * OUT_COLS + tx * 6;
        #pragma unroll
        for (int jj = 0; jj < 3; ++jj) {
            float lo0, hi0, lo1, hi1;
            unpack2(acc2[r][jj * 2 + 0], lo0, hi0);
            unpack2(acc2[r][jj * 2 + 1], lo1, hi1);
            float2 o;
            o.x = lo0 + hi0 + b2[tx * 6 + jj * 2 + 0];
            o.y = lo1 + hi1 + b2[tx * 6 + jj * 2 + 1];
            *reinterpret_cast<float2*>(op + jj * 2) = o;
        }
    }
}

// ---------------------------------------------------------------------------
extern "C" void kernel_launch(void* const* d_in, const int* in_sizes, int n_in,
                              void* d_out, int out_size) {
    const float* x  = (const float*)d_in[0];
    const int*   ei = (const int*)d_in[1];
    const float* W[12];
    for (int i = 0; i < 12; ++i) W[i] = (const float*)d_in[2 + i];
    float* out = (float*)d_out;

    const int SMEM_BYTES = 36864 + 2 * M_TILE * IN_LD * (int)sizeof(float); // 88064
    cudaFuncSetAttribute(fused_layer_kernel,
                         cudaFuncAttributeMaxDynamicSharedMemorySize, SMEM_BYTES);

    // CSR build
    zero_cnt_kernel<<<(N_NODES + 255) / 256, 256>>>();
    count_kernel<<<(N_EDGES + 255) / 256, 256>>>(ei);
    scan_a_kernel<<<SCAN_NB, SCAN_BS>>>();
    scan_b_kernel<<<1, 128>>>();
    scan_c_kernel<<<(N_NODES + 255) / 256, 256>>>();
    fill_kernel<<<(N_EDGES + 255) / 256, 256>>>(ei);

    const int GRID = (N_NODES + M_TILE - 1) / M_TILE;   // 782
    for (int l = 0; l < 3; ++l) {
        const float* cur = (l == 0) ? x : out + (size_t)l * D;
        int cs           = (l == 0) ? D : OUT_COLS;
        float* self0     = (l == 0) ? out : nullptr;    // S0 = x
        float* dst       = out + (size_t)(l + 1) * D;   // S_{l+1}
        fused_layer_kernel<<<GRID, 256, SMEM_BYTES>>>(
            cur, cs, W[4 * l + 0], W[4 * l + 1], W[4 * l + 2], W[4 * l + 3],
            self0, dst);
    }
}